// round 3
// baseline (speedup 1.0000x reference)
#include <cuda_runtime.h>

// Retrace: B=2048, T=512, D=16 (fp32).
// Inputs (metadata order):
//   0: Q                     [B,T,D]
//   1: expected_target_Q     [B,T,D]
//   2: target_Q              [B,T,D]
//   3: rewards               [B,T,D]
//   4: target_policy_probs   [B,T,D]
//   5: behaviour_policy_probs[B,T]
// Output: scalar fp32 = mean((Q[:, :-1] - q_ret)^2)

#define T_DIM 512
#define D_DIM 16
#define GAMMA 0.99f
#define BLOCK 128
#define GROUP 7          // 511 = 7 * 73
#define NGROUPS 73
#define MAX_BLOCKS 1024

__device__ float g_partials[MAX_BLOCKS];

__global__ __launch_bounds__(BLOCK)
void retrace_main(const float* __restrict__ Q,
                  const float* __restrict__ E,
                  const float* __restrict__ TQ,
                  const float* __restrict__ R,
                  const float* __restrict__ TPP,
                  const float* __restrict__ BPP)
{
    const int tid = blockIdx.x * BLOCK + threadIdx.x;
    const int b = tid >> 4;          // / D_DIM
    const int d = tid & 15;          // % D_DIM

    const long base = (long)b * T_DIM * D_DIM + d;

    // Pointers positioned at the first (highest-t) element each stream reads.
    // rewards/Q indexed at t (t = T-2 first), the others at t+1 (= T-1 first).
    const float* pr  = R   + base + (long)(T_DIM - 2) * D_DIM;
    const float* pq  = Q   + base + (long)(T_DIM - 2) * D_DIM;
    const float* pe  = E   + base + (long)(T_DIM - 1) * D_DIM;
    const float* ptq = TQ  + base + (long)(T_DIM - 1) * D_DIM;
    const float* ptp = TPP + base + (long)(T_DIM - 1) * D_DIM;
    const float* pb  = BPP + (long)b * T_DIM + (T_DIM - 1);

    float carry = TQ[base + (long)(T_DIM - 1) * D_DIM];   // target_Q[:, -1]
    float acc = 0.0f;

    for (int g = 0; g < NGROUPS; ++g) {
        float r[GROUP], e[GROUP], tq[GROUP], tp[GROUP], qv[GROUP], bp[GROUP];
        // Independent loads for the whole group — issued before the carry chain.
        #pragma unroll
        for (int k = 0; k < GROUP; ++k) {
            r[k]  = pr [-k * D_DIM];
            qv[k] = pq [-k * D_DIM];
            e[k]  = pe [-k * D_DIM];
            tq[k] = ptq[-k * D_DIM];
            tp[k] = ptp[-k * D_DIM];
            bp[k] = pb [-k];
        }
        // Dependent affine chain + loss accumulation.
        #pragma unroll
        for (int k = 0; k < GROUP; ++k) {
            float c = __expf(fminf(tp[k] - bp[k], 0.0f));
            carry = fmaf(GAMMA, fmaf(c, carry - tq[k], e[k]), r[k]);
            float df = qv[k] - carry;
            acc = fmaf(df, df, acc);
        }
        pr  -= GROUP * D_DIM;
        pq  -= GROUP * D_DIM;
        pe  -= GROUP * D_DIM;
        ptq -= GROUP * D_DIM;
        ptp -= GROUP * D_DIM;
        pb  -= GROUP;
    }

    // Block reduction (deterministic): warp shuffle, then shared across warps.
    #pragma unroll
    for (int off = 16; off > 0; off >>= 1)
        acc += __shfl_xor_sync(0xFFFFFFFFu, acc, off);

    __shared__ float s_warp[BLOCK / 32];
    const int lane = threadIdx.x & 31;
    const int wid  = threadIdx.x >> 5;
    if (lane == 0) s_warp[wid] = acc;
    __syncthreads();
    if (wid == 0) {
        float v = (lane < BLOCK / 32) ? s_warp[lane] : 0.0f;
        #pragma unroll
        for (int off = 2; off > 0; off >>= 1)
            v += __shfl_xor_sync(0xFFFFFFFFu, v, off);
        if (lane == 0) g_partials[blockIdx.x] = v;
    }
}

__global__ void retrace_finalize(float* __restrict__ out, int nblocks, double inv_count)
{
    // Single block; deterministic double-precision sum of block partials.
    __shared__ double s[256];
    double v = 0.0;
    for (int i = threadIdx.x; i < nblocks; i += blockDim.x)
        v += (double)g_partials[i];
    s[threadIdx.x] = v;
    __syncthreads();
    for (int stride = blockDim.x >> 1; stride > 0; stride >>= 1) {
        if (threadIdx.x < stride) s[threadIdx.x] += s[threadIdx.x + stride];
        __syncthreads();
    }
    if (threadIdx.x == 0)
        out[0] = (float)(s[0] * inv_count);
}

extern "C" void kernel_launch(void* const* d_in, const int* in_sizes, int n_in,
                              void* d_out, int out_size)
{
    const float* Q   = (const float*)d_in[0];
    const float* E   = (const float*)d_in[1];
    const float* TQ  = (const float*)d_in[2];
    const float* R   = (const float*)d_in[3];
    const float* TPP = (const float*)d_in[4];
    const float* BPP = (const float*)d_in[5];

    const int B = in_sizes[5] / T_DIM;                 // 2048
    const int total_threads = B * D_DIM;               // 32768
    const int nblocks = total_threads / BLOCK;         // 256

    retrace_main<<<nblocks, BLOCK>>>(Q, E, TQ, R, TPP, BPP);

    const double inv_count = 1.0 / ((double)B * (double)(T_DIM - 1) * (double)D_DIM);
    retrace_finalize<<<1, 256>>>((float*)d_out, nblocks, inv_count);
}

// round 5
// speedup vs baseline: 2.4977x; 2.4977x over previous
#include <cuda_runtime.h>

// Retrace: B=2048, T=512, D=16 (fp32). One thread per (b,d) chain.
// Software-pipelined (double-buffered register groups) streaming scan:
// loads for group g+1 are in flight while the affine carry chain of group g runs.
//
// Inputs (metadata order):
//   0: Q [B,T,D]  1: expected_target_Q [B,T,D]  2: target_Q [B,T,D]
//   3: rewards [B,T,D]  4: target_policy_probs [B,T,D]  5: behaviour_policy_probs [B,T]
// Output: scalar fp32 = mean((Q[:, :-1] - q_ret)^2)

#define T_DIM 512
#define D_DIM 16
#define GAMMA 0.99f
#define BLOCK 128
#define GROUP 7          // 511 = 7 * 73
#define NGROUPS 73
#define NBLOCKS 256      // 2048*16 / 128

__device__ float g_partials[NBLOCKS];
__device__ unsigned int g_ticket;   // zero at load; reset by last block each launch

struct Grp { float r[GROUP], qv[GROUP], e[GROUP], tq[GROUP], tp[GROUP], bp[GROUP]; };

__device__ __forceinline__ void load_grp(Grp& g, int gi,
    const float* __restrict__ pr, const float* __restrict__ pq,
    const float* __restrict__ pe, const float* __restrict__ ptq,
    const float* __restrict__ ptp, const float* __restrict__ pb)
{
    #pragma unroll
    for (int k = 0; k < GROUP; ++k) {
        const int s = gi * GROUP + k;       // step index from the top
        const int o = s * D_DIM;
        g.r[k]  = pr [-o];
        g.qv[k] = pq [-o];
        g.e[k]  = pe [-o];
        g.tq[k] = ptq[-o];
        g.tp[k] = ptp[-o];
        g.bp[k] = pb [-s];
    }
}

__device__ __forceinline__ void compute_grp(const Grp& g, float& carry, float& acc)
{
    #pragma unroll
    for (int k = 0; k < GROUP; ++k) {
        float c = __expf(fminf(g.tp[k] - g.bp[k], 0.0f));
        carry = fmaf(GAMMA, fmaf(c, carry - g.tq[k], g.e[k]), g.r[k]);
        float df = g.qv[k] - carry;
        acc = fmaf(df, df, acc);
    }
}

__global__ __launch_bounds__(BLOCK)
void retrace_main(const float* __restrict__ Q,
                  const float* __restrict__ E,
                  const float* __restrict__ TQ,
                  const float* __restrict__ R,
                  const float* __restrict__ TPP,
                  const float* __restrict__ BPP,
                  float* __restrict__ out,
                  double inv_count)
{
    const int tid = blockIdx.x * BLOCK + threadIdx.x;
    const int b = tid >> 4;
    const int d = tid & 15;

    const long base = (long)b * (T_DIM * D_DIM) + d;

    // Pointers at the first (highest-t) element each stream reads.
    const float* pr  = R   + base + (long)(T_DIM - 2) * D_DIM;   // rewards[t],  t = T-2 .. 0
    const float* pq  = Q   + base + (long)(T_DIM - 2) * D_DIM;   // Q[t]
    const float* pe  = E   + base + (long)(T_DIM - 1) * D_DIM;   // E[t+1]
    const float* ptq = TQ  + base + (long)(T_DIM - 1) * D_DIM;   // TQ[t+1]
    const float* ptp = TPP + base + (long)(T_DIM - 1) * D_DIM;   // TPP[t+1]
    const float* pb  = BPP + (long)b * T_DIM + (T_DIM - 1);      // BPP[t+1]

    float carry = ptq[0];                 // target_Q[:, -1]
    float acc = 0.0f;

    Grp A, Bf;

    // Prologue: group 0 into A.
    load_grp(A, 0, pr, pq, pe, ptq, ptp, pb);

    // Steady state: 2 groups in flight; parity static via manual unroll-by-2.
    // NGROUPS = 73 (odd): loop handles groups 0..71, tail handles 72.
    for (int g = 0; g + 2 <= NGROUPS; g += 2) {
        load_grp(Bf, g + 1, pr, pq, pe, ptq, ptp, pb);
        compute_grp(A, carry, acc);
        if (g + 2 < NGROUPS)
            load_grp(A, g + 2, pr, pq, pe, ptq, ptp, pb);
        compute_grp(Bf, carry, acc);
    }
    compute_grp(A, carry, acc);           // group 72 (loaded in last iteration)

    // Block reduction (fixed order -> deterministic).
    #pragma unroll
    for (int off = 16; off > 0; off >>= 1)
        acc += __shfl_xor_sync(0xFFFFFFFFu, acc, off);

    __shared__ float s_warp[BLOCK / 32];
    const int lane = threadIdx.x & 31;
    const int wid  = threadIdx.x >> 5;
    if (lane == 0) s_warp[wid] = acc;
    __syncthreads();

    __shared__ bool s_last;
    if (threadIdx.x == 0) {
        float v = s_warp[0] + s_warp[1] + s_warp[2] + s_warp[3];
        g_partials[blockIdx.x] = v;
        __threadfence();
        unsigned int t = atomicAdd(&g_ticket, 1u);
        s_last = (t == NBLOCKS - 1);
    }
    __syncthreads();

    // Last-arriving block finalizes: fixed-order double sum -> deterministic.
    if (s_last) {
        __shared__ double s_d[BLOCK];
        double v = 0.0;
        for (int i = threadIdx.x; i < NBLOCKS; i += BLOCK)
            v += (double)g_partials[i];
        s_d[threadIdx.x] = v;
        __syncthreads();
        for (int stride = BLOCK >> 1; stride > 0; stride >>= 1) {
            if (threadIdx.x < stride) s_d[threadIdx.x] += s_d[threadIdx.x + stride];
            __syncthreads();
        }
        if (threadIdx.x == 0) {
            out[0] = (float)(s_d[0] * inv_count);
            g_ticket = 0;                 // reset for next (graph-replayed) launch
        }
    }
}

extern "C" void kernel_launch(void* const* d_in, const int* in_sizes, int n_in,
                              void* d_out, int out_size)
{
    const float* Q   = (const float*)d_in[0];
    const float* E   = (const float*)d_in[1];
    const float* TQ  = (const float*)d_in[2];
    const float* R   = (const float*)d_in[3];
    const float* TPP = (const float*)d_in[4];
    const float* BPP = (const float*)d_in[5];

    const int B = in_sizes[5] / T_DIM;                 // 2048
    const double inv_count =
        1.0 / ((double)B * (double)(T_DIM - 1) * (double)D_DIM);

    retrace_main<<<NBLOCKS, BLOCK>>>(Q, E, TQ, R, TPP, BPP,
                                     (float*)d_out, inv_count);
}

// round 6
// speedup vs baseline: 3.1831x; 1.2744x over previous
#include <cuda_runtime.h>

// Retrace: B=2048, T=512, D=16 (fp32).
// Segmented affine scan: each (chain, segment) thread computes the segment's
// affine composition carry_out = A*x + B and its loss as a quadratic in x:
//   loss_seg(x) = sdd - 2*x*sAd + x^2*sAA.
// Phase 2 chains segments (x <- A*x + B), sums quadratics, reduces to the mean.
//
// Inputs (metadata order):
//   0: Q [B,T,D]  1: expected_target_Q [B,T,D]  2: target_Q [B,T,D]
//   3: rewards [B,T,D]  4: target_policy_probs [B,T,D]  5: behaviour_policy_probs [B,T]
// Output: scalar fp32 = mean((Q[:, :-1] - q_ret)^2)

#define T_DIM 512
#define D_DIM 16
#define GAMMA 0.99f
#define BLOCK 128
#define SEG 8
#define SEGLEN 64                       // steps/segment; last segment has 63 (511 total)
#define NCHAINS (2048 * 16)             // 32768
#define NBLK1 ((NCHAINS * SEG) / BLOCK) // 2048
#define NBLK2 (NCHAINS / BLOCK)         // 256

__device__ float g_sAA[SEG * NCHAINS];
__device__ float g_sAd[SEG * NCHAINS];
__device__ float g_sdd[SEG * NCHAINS];
__device__ float g_A  [SEG * NCHAINS];
__device__ float g_B  [SEG * NCHAINS];
__device__ float g_partials[NBLK2];
__device__ unsigned int g_ticket;       // zero-init; reset by finalizer each launch

// ---------------- Phase 1: per-(chain,segment) affine summary ----------------
__global__ __launch_bounds__(BLOCK)
void retrace_seg(const float* __restrict__ Q,
                 const float* __restrict__ E,
                 const float* __restrict__ TQ,
                 const float* __restrict__ R,
                 const float* __restrict__ TPP,
                 const float* __restrict__ BPP)
{
    const int tid = blockIdx.x * BLOCK + threadIdx.x;
    const int cid = tid & (NCHAINS - 1);     // chain id (d fastest -> coalesced)
    const int s   = tid >> 15;               // segment id, 0..7
    const int b   = cid >> 4;
    const int d   = cid & 15;

    const int lo = s * SEGLEN;
    const int hi = (s == SEG - 1) ? (T_DIM - 2) : (lo + SEGLEN - 1);
    const int n  = hi - lo + 1;              // 64, or 63 for s=7

    const long base = (long)b * (T_DIM * D_DIM) + d;
    const float* pr  = R   + base + (long)hi * D_DIM;        // rewards[t]
    const float* pq  = Q   + base + (long)hi * D_DIM;        // Q[t]
    const float* pe  = E   + base + (long)(hi + 1) * D_DIM;  // E[t+1]
    const float* ptq = TQ  + base + (long)(hi + 1) * D_DIM;  // TQ[t+1]
    const float* ptp = TPP + base + (long)(hi + 1) * D_DIM;  // TPP[t+1]
    const float* pb  = BPP + (long)b * T_DIM + (hi + 1);     // BPP[t+1]

    // carry = A*x + B over the segment; loss quadratic accumulators.
    float A = 1.0f, Bv = 0.0f;
    float sAA = 0.0f, sAd = 0.0f, sdd = 0.0f;

    int i = 0;
    for (; i + 4 <= n; i += 4) {
        float r[4], qv[4], e[4], tq[4], tp[4], bp[4];
        #pragma unroll
        for (int k = 0; k < 4; ++k) {
            const int o = (i + k) * D_DIM;
            r[k]  = pr [-o];
            qv[k] = pq [-o];
            e[k]  = pe [-o];
            tq[k] = ptq[-o];
            tp[k] = ptp[-o];
            bp[k] = pb [-(i + k)];
        }
        #pragma unroll
        for (int k = 0; k < 4; ++k) {
            float c  = __expf(fminf(tp[k] - bp[k], 0.0f));
            float m  = GAMMA * c;
            float t1 = fmaf(GAMMA, e[k], r[k]);      // r + g*e
            Bv = fmaf(m, Bv - tq[k], t1);            // B' = m*(B - tq) + r + g*e
            A  = m * A;                              // A' = m*A
            float dv = qv[k] - Bv;                   // df = dv - A'*x
            sdd = fmaf(dv, dv, sdd);
            sAd = fmaf(A, dv, sAd);
            sAA = fmaf(A, A, sAA);
        }
    }
    for (; i < n; ++i) {                             // remainder (3 steps for s=7)
        const int o = i * D_DIM;
        float c  = __expf(fminf(ptp[-o] - pb[-i], 0.0f));
        float m  = GAMMA * c;
        float t1 = fmaf(GAMMA, pe[-o], pr[-o]);
        Bv = fmaf(m, Bv - ptq[-o], t1);
        A  = m * A;
        float dv = pq[-o] - Bv;
        sdd = fmaf(dv, dv, sdd);
        sAd = fmaf(A, dv, sAd);
        sAA = fmaf(A, A, sAA);
    }

    const int idx = s * NCHAINS + cid;               // [seg][chain] -> phase-2 coalesced
    g_sAA[idx] = sAA;
    g_sAd[idx] = sAd;
    g_sdd[idx] = sdd;
    g_A[idx]   = A;
    g_B[idx]   = Bv;
}

// ------------- Phase 2: chain segments, reduce, finalize (fused) -------------
__global__ __launch_bounds__(BLOCK)
void retrace_combine(const float* __restrict__ TQ,
                     float* __restrict__ out,
                     double inv_count)
{
    const int cid = blockIdx.x * BLOCK + threadIdx.x;
    const int b = cid >> 4;
    const int d = cid & 15;

    // x = target_Q[:, -1]
    float x = TQ[(long)b * (T_DIM * D_DIM) + (long)(T_DIM - 1) * D_DIM + d];

    float loss = 0.0f;
    #pragma unroll
    for (int s = SEG - 1; s >= 0; --s) {             // latest times first
        const int idx = s * NCHAINS + cid;
        const float aa = g_sAA[idx];
        const float ad = g_sAd[idx];
        const float dd = g_sdd[idx];
        const float A  = g_A[idx];
        const float Bv = g_B[idx];
        loss += fmaf(x, fmaf(x, aa, -2.0f * ad), dd);
        x = fmaf(A, x, Bv);
    }

    // Deterministic block reduction.
    #pragma unroll
    for (int off = 16; off > 0; off >>= 1)
        loss += __shfl_xor_sync(0xFFFFFFFFu, loss, off);

    __shared__ float s_warp[BLOCK / 32];
    const int lane = threadIdx.x & 31;
    const int wid  = threadIdx.x >> 5;
    if (lane == 0) s_warp[wid] = loss;
    __syncthreads();

    __shared__ bool s_last;
    if (threadIdx.x == 0) {
        g_partials[blockIdx.x] = s_warp[0] + s_warp[1] + s_warp[2] + s_warp[3];
        __threadfence();
        unsigned int t = atomicAdd(&g_ticket, 1u);
        s_last = (t == NBLK2 - 1);
    }
    __syncthreads();

    if (s_last) {
        __shared__ double s_d[BLOCK];
        double v = 0.0;
        for (int i = threadIdx.x; i < NBLK2; i += BLOCK)
            v += (double)g_partials[i];
        s_d[threadIdx.x] = v;
        __syncthreads();
        for (int stride = BLOCK >> 1; stride > 0; stride >>= 1) {
            if (threadIdx.x < stride) s_d[threadIdx.x] += s_d[threadIdx.x + stride];
            __syncthreads();
        }
        if (threadIdx.x == 0) {
            out[0] = (float)(s_d[0] * inv_count);
            g_ticket = 0;                            // reset for next graph replay
        }
    }
}

extern "C" void kernel_launch(void* const* d_in, const int* in_sizes, int n_in,
                              void* d_out, int out_size)
{
    const float* Q   = (const float*)d_in[0];
    const float* E   = (const float*)d_in[1];
    const float* TQ  = (const float*)d_in[2];
    const float* R   = (const float*)d_in[3];
    const float* TPP = (const float*)d_in[4];
    const float* BPP = (const float*)d_in[5];

    const int B = in_sizes[5] / T_DIM;               // 2048
    const double inv_count =
        1.0 / ((double)B * (double)(T_DIM - 1) * (double)D_DIM);

    retrace_seg<<<NBLK1, BLOCK>>>(Q, E, TQ, R, TPP, BPP);
    retrace_combine<<<NBLK2, BLOCK>>>(TQ, (float*)d_out, inv_count);
}